// round 1
// baseline (speedup 1.0000x reference)
#include <cuda_runtime.h>

#define EL   32
#define RR   256
#define AZ   128
#define NB   16
#define NCELL (EL*RR*AZ)          // 1,048,576 cells per batch
#define NVOX  (320*320*80)        // 8,192,000 voxels per batch
#define N4    ((NB*NVOX)/4)       // float4 count of output

__device__ int g_idx64;           // 1 if index buffer is int64, 0 if int32

// ---------------------------------------------------------------------------
// Detect index dtype: int64 values (all < NVOX) vs int32 misread as int64
// (which yields ~4M * 2^32 garbage). Deterministic, same answer every call.
// ---------------------------------------------------------------------------
__global__ void detect_idx_dtype(const long long* __restrict__ p)
{
    bool ok = true;
#pragma unroll
    for (int k = 0; k < 8; k++) {
        long long v = p[k];
        if (v < 0 || v >= (long long)NVOX) ok = false;
    }
    g_idx64 = ok ? 1 : 0;
}

// ---------------------------------------------------------------------------
// Zero the full output grid (poisoned before timing; replays accumulate
// otherwise). Pure streaming stores -> HBM write bound.
// ---------------------------------------------------------------------------
__global__ __launch_bounds__(256) void zero_kernel(float4* __restrict__ out)
{
    int i = blockIdx.x * blockDim.x + threadIdx.x;
    int stride = gridDim.x * blockDim.x;
    const float4 z = make_float4(0.f, 0.f, 0.f, 0.f);
    for (; i < N4; i += stride) out[i] = z;
}

// ---------------------------------------------------------------------------
// Scatter: each thread owns a 2x2 (el,r) quad at one azimuth. Range bins are
// 0.125m vs 0.25m voxels and el spacing < 0.25m for r<13m, so the 4 cells
// usually collapse to 1 voxel -> dedup once (indices are batch-invariant),
// then per batch do 1..4 atomicAdd (compiles to RED.E.ADD.F32, no return).
// Loads are az-contiguous across the warp -> fully coalesced.
// ---------------------------------------------------------------------------
__global__ __launch_bounds__(256) void scatter_kernel(
    const float* __restrict__ polar,
    const void*  __restrict__ idxbuf,
    float*       __restrict__ out)
{
    const int NT = (EL/2) * (RR/2) * AZ;     // 262,144 threads
    int t = blockIdx.x * blockDim.x + threadIdx.x;
    if (t >= NT) return;

    int az  = t & (AZ - 1);
    int r2  = (t >> 7) & (RR/2 - 1);
    int el2 = t >> 14;

    int i0 = ((el2 * 2) * RR + r2 * 2) * AZ + az;   // (el  , r  )
    int i1 = i0 + AZ;                               // (el  , r+1)
    int i2 = i0 + RR * AZ;                          // (el+1, r  )
    int i3 = i2 + AZ;                               // (el+1, r+1)

    int idx0, idx1, idx2, idx3;
    if (g_idx64) {
        const long long* p = (const long long*)idxbuf;
        idx0 = (int)p[i0]; idx1 = (int)p[i1];
        idx2 = (int)p[i2]; idx3 = (int)p[i3];
    } else {
        const int* p = (const int*)idxbuf;
        idx0 = p[i0]; idx1 = p[i1]; idx2 = p[i2]; idx3 = p[i3];
    }

    // Canonical-slot map (earliest duplicate wins). Batch-invariant.
    const int m1 = (idx1 == idx0) ? 0 : 1;
    const int m2 = (idx2 == idx0) ? 0 : ((idx2 == idx1) ? 1 : 2);
    const int m3 = (idx3 == idx0) ? 0 : ((idx3 == idx1) ? 1 :
                   ((idx3 == idx2) ? 2 : 3));

#pragma unroll 4
    for (int b = 0; b < NB; b++) {
        const float* pf = polar + b * NCELL;
        float v0 = pf[i0], v1 = pf[i1], v2 = pf[i2], v3 = pf[i3];

        float a0 = v0, a1 = v1, a2 = v2, a3 = v3;
        if (m1 == 0) a0 += v1;
        if (m2 == 0) a0 += v2; else if (m2 == 1) a1 += v2;
        if (m3 == 0) a0 += v3; else if (m3 == 1) a1 += v3;
        else if (m3 == 2) a2 += v3;

        float* ob = out + b * NVOX;
        atomicAdd(ob + idx0, a0);
        if (m1 == 1) atomicAdd(ob + idx1, a1);
        if (m2 == 2) atomicAdd(ob + idx2, a2);
        if (m3 == 3) atomicAdd(ob + idx3, a3);
    }
}

extern "C" void kernel_launch(void* const* d_in, const int* in_sizes, int n_in,
                              void* d_out, int out_size)
{
    const float* polar = (const float*)d_in[0];
    const void*  idx   = d_in[1];
    float*       out   = (float*)d_out;

    detect_idx_dtype<<<1, 1>>>((const long long*)idx);
    zero_kernel<<<8192, 256>>>((float4*)out);

    const int NT = (EL/2) * (RR/2) * AZ;
    scatter_kernel<<<NT / 256, 256>>>(polar, idx, out);
}

// round 2
// speedup vs baseline: 1.0055x; 1.0055x over previous
#include <cuda_runtime.h>

#define EL   32
#define RR   256
#define AZ   128
#define NB   16
#define NCELL (EL*RR*AZ)          // 1,048,576 cells per batch
#define NVOX  (320*320*80)        // 8,192,000 voxels per batch
#define N4    ((NB*NVOX)/4)       // float4 count of output

__device__ int g_idx64;           // 1 if index buffer is int64, 0 if int32

// ---------------------------------------------------------------------------
// Detect index dtype: int64 values (all < NVOX) vs int32 misread as int64
// (which yields ~4M * 2^32 garbage). Deterministic, same answer every call.
// ---------------------------------------------------------------------------
__global__ void detect_idx_dtype(const long long* __restrict__ p)
{
    bool ok = true;
#pragma unroll
    for (int k = 0; k < 8; k++) {
        long long v = p[k];
        if (v < 0 || v >= (long long)NVOX) ok = false;
    }
    g_idx64 = ok ? 1 : 0;
}

// ---------------------------------------------------------------------------
// Zero the full output grid (poisoned before timing; replays accumulate
// otherwise). Pure streaming stores -> HBM write bound.
// ---------------------------------------------------------------------------
__global__ __launch_bounds__(256) void zero_kernel(float4* __restrict__ out)
{
    int i = blockIdx.x * blockDim.x + threadIdx.x;
    int stride = gridDim.x * blockDim.x;
    const float4 z = make_float4(0.f, 0.f, 0.f, 0.f);
    for (; i < N4; i += stride) out[i] = z;
}

// ---------------------------------------------------------------------------
// Scatter: each thread owns a 2x2 (el,r) quad at one azimuth. Range bins are
// 0.125m vs 0.25m voxels and el spacing < 0.25m for r<13m, so the 4 cells
// usually collapse to 1 voxel -> dedup once (indices are batch-invariant),
// then per batch do 1..4 atomicAdd (compiles to RED.E.ADD.F32, no return).
// Loads are az-contiguous across the warp -> fully coalesced.
// ---------------------------------------------------------------------------
__global__ __launch_bounds__(256) void scatter_kernel(
    const float* __restrict__ polar,
    const void*  __restrict__ idxbuf,
    float*       __restrict__ out)
{
    const int NT = (EL/2) * (RR/2) * AZ;     // 262,144 threads
    int t = blockIdx.x * blockDim.x + threadIdx.x;
    if (t >= NT) return;

    int az  = t & (AZ - 1);
    int r2  = (t >> 7) & (RR/2 - 1);
    int el2 = t >> 14;

    int i0 = ((el2 * 2) * RR + r2 * 2) * AZ + az;   // (el  , r  )
    int i1 = i0 + AZ;                               // (el  , r+1)
    int i2 = i0 + RR * AZ;                          // (el+1, r  )
    int i3 = i2 + AZ;                               // (el+1, r+1)

    int idx0, idx1, idx2, idx3;
    if (g_idx64) {
        const long long* p = (const long long*)idxbuf;
        idx0 = (int)p[i0]; idx1 = (int)p[i1];
        idx2 = (int)p[i2]; idx3 = (int)p[i3];
    } else {
        const int* p = (const int*)idxbuf;
        idx0 = p[i0]; idx1 = p[i1]; idx2 = p[i2]; idx3 = p[i3];
    }

    // Canonical-slot map (earliest duplicate wins). Batch-invariant.
    const int m1 = (idx1 == idx0) ? 0 : 1;
    const int m2 = (idx2 == idx0) ? 0 : ((idx2 == idx1) ? 1 : 2);
    const int m3 = (idx3 == idx0) ? 0 : ((idx3 == idx1) ? 1 :
                   ((idx3 == idx2) ? 2 : 3));

#pragma unroll 4
    for (int b = 0; b < NB; b++) {
        const float* pf = polar + b * NCELL;
        float v0 = pf[i0], v1 = pf[i1], v2 = pf[i2], v3 = pf[i3];

        float a0 = v0, a1 = v1, a2 = v2, a3 = v3;
        if (m1 == 0) a0 += v1;
        if (m2 == 0) a0 += v2; else if (m2 == 1) a1 += v2;
        if (m3 == 0) a0 += v3; else if (m3 == 1) a1 += v3;
        else if (m3 == 2) a2 += v3;

        float* ob = out + b * NVOX;
        atomicAdd(ob + idx0, a0);
        if (m1 == 1) atomicAdd(ob + idx1, a1);
        if (m2 == 2) atomicAdd(ob + idx2, a2);
        if (m3 == 3) atomicAdd(ob + idx3, a3);
    }
}

extern "C" void kernel_launch(void* const* d_in, const int* in_sizes, int n_in,
                              void* d_out, int out_size)
{
    const float* polar = (const float*)d_in[0];
    const void*  idx   = d_in[1];
    float*       out   = (float*)d_out;

    detect_idx_dtype<<<1, 1>>>((const long long*)idx);
    zero_kernel<<<8192, 256>>>((float4*)out);

    const int NT = (EL/2) * (RR/2) * AZ;
    scatter_kernel<<<NT / 256, 256>>>(polar, idx, out);
}

// round 3
// speedup vs baseline: 1.0062x; 1.0008x over previous
#include <cuda_runtime.h>

#define EL   32
#define RR   256
#define AZ   128
#define NB   16
#define NCELL (EL*RR*AZ)          // 1,048,576 cells per batch
#define NVOX  (320*320*80)        // 8,192,000 voxels per batch
#define N4    ((NB*NVOX)/4)       // float4 count of output

__device__ int g_idx64;           // 1 if index buffer is int64, 0 if int32

// ---------------------------------------------------------------------------
// Detect index dtype: int64 values (all < NVOX) vs int32 misread as int64
// (which yields ~4M * 2^32 garbage). Deterministic, same answer every call.
// ---------------------------------------------------------------------------
__global__ void detect_idx_dtype(const long long* __restrict__ p)
{
    bool ok = true;
#pragma unroll
    for (int k = 0; k < 8; k++) {
        long long v = p[k];
        if (v < 0 || v >= (long long)NVOX) ok = false;
    }
    g_idx64 = ok ? 1 : 0;
}

// ---------------------------------------------------------------------------
// Zero the full output grid (poisoned before timing; replays accumulate
// otherwise). Pure streaming stores -> HBM write bound.
// ---------------------------------------------------------------------------
__global__ __launch_bounds__(256) void zero_kernel(float4* __restrict__ out)
{
    int i = blockIdx.x * blockDim.x + threadIdx.x;
    int stride = gridDim.x * blockDim.x;
    const float4 z = make_float4(0.f, 0.f, 0.f, 0.f);
    for (; i < N4; i += stride) out[i] = z;
}

// ---------------------------------------------------------------------------
// Scatter: each thread owns a 2x2 (el,r) quad at one azimuth. Range bins are
// 0.125m vs 0.25m voxels and el spacing < 0.25m for r<13m, so the 4 cells
// usually collapse to 1 voxel -> dedup once (indices are batch-invariant),
// then per batch do 1..4 atomicAdd (compiles to RED.E.ADD.F32, no return).
// Loads are az-contiguous across the warp -> fully coalesced.
// ---------------------------------------------------------------------------
__global__ __launch_bounds__(256) void scatter_kernel(
    const float* __restrict__ polar,
    const void*  __restrict__ idxbuf,
    float*       __restrict__ out)
{
    const int NT = (EL/2) * (RR/2) * AZ;     // 262,144 threads
    int t = blockIdx.x * blockDim.x + threadIdx.x;
    if (t >= NT) return;

    int az  = t & (AZ - 1);
    int r2  = (t >> 7) & (RR/2 - 1);
    int el2 = t >> 14;

    int i0 = ((el2 * 2) * RR + r2 * 2) * AZ + az;   // (el  , r  )
    int i1 = i0 + AZ;                               // (el  , r+1)
    int i2 = i0 + RR * AZ;                          // (el+1, r  )
    int i3 = i2 + AZ;                               // (el+1, r+1)

    int idx0, idx1, idx2, idx3;
    if (g_idx64) {
        const long long* p = (const long long*)idxbuf;
        idx0 = (int)p[i0]; idx1 = (int)p[i1];
        idx2 = (int)p[i2]; idx3 = (int)p[i3];
    } else {
        const int* p = (const int*)idxbuf;
        idx0 = p[i0]; idx1 = p[i1]; idx2 = p[i2]; idx3 = p[i3];
    }

    // Canonical-slot map (earliest duplicate wins). Batch-invariant.
    const int m1 = (idx1 == idx0) ? 0 : 1;
    const int m2 = (idx2 == idx0) ? 0 : ((idx2 == idx1) ? 1 : 2);
    const int m3 = (idx3 == idx0) ? 0 : ((idx3 == idx1) ? 1 :
                   ((idx3 == idx2) ? 2 : 3));

#pragma unroll 4
    for (int b = 0; b < NB; b++) {
        const float* pf = polar + b * NCELL;
        float v0 = pf[i0], v1 = pf[i1], v2 = pf[i2], v3 = pf[i3];

        float a0 = v0, a1 = v1, a2 = v2, a3 = v3;
        if (m1 == 0) a0 += v1;
        if (m2 == 0) a0 += v2; else if (m2 == 1) a1 += v2;
        if (m3 == 0) a0 += v3; else if (m3 == 1) a1 += v3;
        else if (m3 == 2) a2 += v3;

        float* ob = out + b * NVOX;
        atomicAdd(ob + idx0, a0);
        if (m1 == 1) atomicAdd(ob + idx1, a1);
        if (m2 == 2) atomicAdd(ob + idx2, a2);
        if (m3 == 3) atomicAdd(ob + idx3, a3);
    }
}

extern "C" void kernel_launch(void* const* d_in, const int* in_sizes, int n_in,
                              void* d_out, int out_size)
{
    const float* polar = (const float*)d_in[0];
    const void*  idx   = d_in[1];
    float*       out   = (float*)d_out;

    detect_idx_dtype<<<1, 1>>>((const long long*)idx);
    zero_kernel<<<8192, 256>>>((float4*)out);

    const int NT = (EL/2) * (RR/2) * AZ;
    scatter_kernel<<<NT / 256, 256>>>(polar, idx, out);
}